// round 1
// baseline (speedup 1.0000x reference)
#include <cuda_runtime.h>
#include <cuda_bf16.h>
#include <cstdint>

// Problem constants
#define NB   64      // batch
#define TT   512     // time steps
#define DD   512     // input dim
#define HH   512     // hidden dim
#define G3   1536    // 3*H

// Scratch (device globals: allocation-free)
__device__ float g_xm[(size_t)2 * NB * TT * G3];   // [dir][n][t][3H], bias folded in
__device__ float g_h[2 * 2 * NB * HH];             // [dir][parity][n][h] ping-pong

// -----------------------------------------------------------------------------
// Zero the h ping-pong buffers (only parity 0 strictly needed; zero all)
// -----------------------------------------------------------------------------
__global__ void zero_h_kernel(float* h) {
    int i = blockIdx.x * blockDim.x + threadIdx.x;   // 128*256 = 32768 float4s
    float4 z = make_float4(0.f, 0.f, 0.f, 0.f);
    reinterpret_cast<float4*>(h)[i] = z;
}

// -----------------------------------------------------------------------------
// Input projection GEMM: xm[dir][m][c] = sum_k A[m][k] * Wx[k][c] + bias[c]
//   m = n*512 + t ; for dir==1 (backward) the time index is flipped on read.
//   A: x [64][512][512], Wx: [512][1536]
// Tiling: BM=128, BN=128, BK=16, 256 threads, 8x8 per-thread microtile.
// Grid: (1536/128=12, 32768/128=256, 2)
// -----------------------------------------------------------------------------
#define BM 128
#define BN 128
#define BK 16

__global__ __launch_bounds__(256) void sgemm_xm_kernel(
    const float* __restrict__ x,
    const float* __restrict__ Wx_f, const float* __restrict__ Wx_b,
    const float* __restrict__ b_f,  const float* __restrict__ b_b,
    float* __restrict__ xm)
{
    const int dir = blockIdx.z;
    const float* __restrict__ Wx   = dir ? Wx_b : Wx_f;
    const float* __restrict__ bias = dir ? b_b  : b_f;
    float* __restrict__ C = xm + (size_t)dir * (NB * TT) * G3;

    __shared__ float As[BK][BM + 4];   // transposed A tile, padded
    __shared__ float Bs[BK][BN];

    const int t  = threadIdx.x;
    const int tx = t & 15;           // 0..15  (col group)
    const int ty = t >> 4;           // 0..15  (row group)

    const int mBase = blockIdx.y * BM;
    const int nBase = blockIdx.x * BN;

    // A-load mapping: thread loads rows {aRow, aRow+64}, 4 k-values each
    const int aRow = t >> 2;          // 0..63
    const int aK   = (t & 3) << 2;    // 0,4,8,12
    // B-load mapping: thread loads k rows {bRow, bRow+8}, 4 cols
    const int bRow = t >> 5;          // 0..7
    const int bCol = (t & 31) << 2;   // 0..124

    float acc[8][8];
#pragma unroll
    for (int i = 0; i < 8; i++)
#pragma unroll
        for (int j = 0; j < 8; j++) acc[i][j] = 0.f;

    for (int k0 = 0; k0 < DD; k0 += BK) {
        // ---- load A tile (transposed into As) ----
#pragma unroll
        for (int h = 0; h < 2; h++) {
            const int m   = mBase + aRow + h * 64;
            const int n   = m >> 9;          // m / 512
            const int tt0 = m & 511;         // m % 512
            const int ts  = dir ? (TT - 1 - tt0) : tt0;
            const float4 v = *reinterpret_cast<const float4*>(
                &x[((size_t)n * TT + ts) * DD + k0 + aK]);
            As[aK + 0][aRow + h * 64] = v.x;
            As[aK + 1][aRow + h * 64] = v.y;
            As[aK + 2][aRow + h * 64] = v.z;
            As[aK + 3][aRow + h * 64] = v.w;
        }
        // ---- load B tile ----
#pragma unroll
        for (int h = 0; h < 2; h++) {
            const int kk = bRow + h * 8;
            *reinterpret_cast<float4*>(&Bs[kk][bCol]) =
                *reinterpret_cast<const float4*>(
                    &Wx[(size_t)(k0 + kk) * G3 + nBase + bCol]);
        }
        __syncthreads();

#pragma unroll
        for (int kk = 0; kk < BK; kk++) {
            float ra[8], rb[8];
#pragma unroll
            for (int i = 0; i < 8; i += 4) {
                float4 v = *reinterpret_cast<const float4*>(&As[kk][ty * 8 + i]);
                ra[i] = v.x; ra[i + 1] = v.y; ra[i + 2] = v.z; ra[i + 3] = v.w;
            }
#pragma unroll
            for (int j = 0; j < 8; j += 4) {
                float4 v = *reinterpret_cast<const float4*>(&Bs[kk][tx * 8 + j]);
                rb[j] = v.x; rb[j + 1] = v.y; rb[j + 2] = v.z; rb[j + 3] = v.w;
            }
#pragma unroll
            for (int i = 0; i < 8; i++)
#pragma unroll
                for (int j = 0; j < 8; j++)
                    acc[i][j] += ra[i] * rb[j];
        }
        __syncthreads();
    }

    // ---- write C with folded bias ----
#pragma unroll
    for (int i = 0; i < 8; i++) {
        const int m = mBase + ty * 8 + i;
#pragma unroll
        for (int j = 0; j < 8; j += 4) {
            const int c = nBase + tx * 8 + j;
            float4 v;
            v.x = acc[i][j + 0] + bias[c + 0];
            v.y = acc[i][j + 1] + bias[c + 1];
            v.z = acc[i][j + 2] + bias[c + 2];
            v.w = acc[i][j + 3] + bias[c + 3];
            *reinterpret_cast<float4*>(&C[(size_t)m * G3 + c]) = v;
        }
    }
}

// -----------------------------------------------------------------------------
// One GRU time step. Grid: (64 j-blocks, 2 dirs), 256 threads.
// Each block owns 8 hidden units j0..j0+7 of one direction:
//   computes hz/hr/hg = h_prev @ W_h[:, {j, H+j, 2H+j}], then gates, then
//   writes h_t to the ping-pong buffer and the output.
// SMEM: h_s[512][64] transposed h_prev (128KB) + w_s[512][24] (48KB).
// Split-K across 8 warps (64 k each); lane covers rows {2l, 2l+1} x 24 cols.
// -----------------------------------------------------------------------------
#define STEP_SMEM_FLOATS (512 * 64 + 512 * 24)
#define STEP_SMEM_BYTES  (STEP_SMEM_FLOATS * 4)

__global__ __launch_bounds__(256) void gru_step_kernel(
    const float* __restrict__ Wh_f, const float* __restrict__ Wh_b,
    const float* __restrict__ xm,   float* __restrict__ h_buf,
    float* __restrict__ out, int s)
{
    extern __shared__ float sm[];
    float* h_s = sm;                 // [512][64]
    float* w_s = sm + 512 * 64;      // [512][24]

    const int dir = blockIdx.y;
    const int j0  = blockIdx.x * 8;
    const float* __restrict__ Wh = dir ? Wh_b : Wh_f;

    const int p = s & 1;
    const float* __restrict__ hprev = h_buf + ((size_t)dir * 2 + p)       * (NB * HH);
    float*       __restrict__ hnext = h_buf + ((size_t)dir * 2 + (p ^ 1)) * (NB * HH);

    const int t = threadIdx.x;

    // ---- stage h_prev transposed: h_s[k][n] = hprev[n*512 + k] ----
    {
        const int n  = t & 63;
        const int kb = (t >> 6) << 2;   // 0,4,8,12
        for (int k = kb; k < HH; k += 16) {
            float4 v = *reinterpret_cast<const float4*>(&hprev[n * HH + k]);
            h_s[(k + 0) * 64 + n] = v.x;
            h_s[(k + 1) * 64 + n] = v.y;
            h_s[(k + 2) * 64 + n] = v.z;
            h_s[(k + 3) * 64 + n] = v.w;
        }
    }
    // ---- stage W slice: w_s[k][g*8+jj] = Wh[k][g*512 + j0 + jj] ----
    for (int i = t; i < 512 * 24; i += 256) {
        const int k  = i / 24;
        const int c  = i - k * 24;
        const int g  = c >> 3;
        const int jj = c & 7;
        w_s[i] = Wh[(size_t)k * G3 + g * HH + j0 + jj];
    }
    __syncthreads();

    // ---- split-K accumulation ----
    const int w = t >> 5;       // warp 0..7 -> k chunk
    const int l = t & 31;       // lane -> rows {2l, 2l+1}
    float acc0[24], acc1[24];
#pragma unroll
    for (int c = 0; c < 24; c++) { acc0[c] = 0.f; acc1[c] = 0.f; }

    const int kbeg = w * 64;
#pragma unroll 2
    for (int k = kbeg; k < kbeg + 64; k++) {
        const float2 hv = *reinterpret_cast<const float2*>(&h_s[k * 64 + 2 * l]);
        const float* wr = &w_s[k * 24];
#pragma unroll
        for (int c = 0; c < 24; c += 4) {
            const float4 wv = *reinterpret_cast<const float4*>(&wr[c]);
            acc0[c + 0] += hv.x * wv.x;  acc1[c + 0] += hv.y * wv.x;
            acc0[c + 1] += hv.x * wv.y;  acc1[c + 1] += hv.y * wv.y;
            acc0[c + 2] += hv.x * wv.z;  acc1[c + 2] += hv.y * wv.z;
            acc0[c + 3] += hv.x * wv.w;  acc1[c + 3] += hv.y * wv.w;
        }
    }
    __syncthreads();   // all reads of h_s done

    // ---- write partials into h_s region: part[w][c][row] ----
#pragma unroll
    for (int c = 0; c < 24; c++) {
        h_s[w * 1536 + c * 64 + 2 * l]     = acc0[c];
        h_s[w * 1536 + c * 64 + 2 * l + 1] = acc1[c];
    }
    __syncthreads();

    // ---- reduce 8 warps into r_s[c][n] (reuse w_s region) ----
    float* r_s = w_s;
    for (int o = t; o < 1536; o += 256) {
        float sum = 0.f;
#pragma unroll
        for (int ww = 0; ww < 8; ww++) sum += h_s[ww * 1536 + o];
        r_s[o] = sum;
    }
    __syncthreads();

    // ---- gates: 512 (n, jj) pairs, 2 per thread ----
    const int t_out = dir ? (TT - 1 - s) : s;
#pragma unroll
    for (int pi = 0; pi < 2; pi++) {
        const int pair = t + pi * 256;
        const int n  = pair >> 3;
        const int jj = pair & 7;
        const int j  = j0 + jj;

        const float hz = r_s[jj * 64 + n];
        const float hr = r_s[(8 + jj) * 64 + n];
        const float hg = r_s[(16 + jj) * 64 + n];

        const float* xb = xm + (((size_t)dir * NB + n) * TT + s) * G3;
        const float xz = xb[j];
        const float xr = xb[HH + j];
        const float xg = xb[2 * HH + j];
        const float hp = hprev[n * HH + j];

        const float z = 1.f / (1.f + __expf(-(xz + hz)));
        const float r = 1.f / (1.f + __expf(-(xr + hr)));
        const float g = tanhf(xg + r * hg);
        const float ht = (1.f - z) * g + z * hp;

        hnext[n * HH + j] = ht;
        out[((size_t)n * TT + t_out) * (2 * HH) + dir * HH + j] = ht;
    }
}

// -----------------------------------------------------------------------------
// Launch
// -----------------------------------------------------------------------------
extern "C" void kernel_launch(void* const* d_in, const int* in_sizes, int n_in,
                              void* d_out, int out_size)
{
    (void)in_sizes; (void)n_in; (void)out_size;
    const float* x   = (const float*)d_in[0];
    const float* Wxf = (const float*)d_in[1];
    const float* Whf = (const float*)d_in[2];
    const float* bf  = (const float*)d_in[3];
    const float* Wxb = (const float*)d_in[4];
    const float* Whb = (const float*)d_in[5];
    const float* bb  = (const float*)d_in[6];
    float* out = (float*)d_out;

    float *xm, *hb;
    cudaGetSymbolAddress((void**)&xm, g_xm);
    cudaGetSymbolAddress((void**)&hb, g_h);

    cudaFuncSetAttribute(gru_step_kernel,
                         cudaFuncAttributeMaxDynamicSharedMemorySize,
                         STEP_SMEM_BYTES);

    // 1) h0 = 0
    zero_h_kernel<<<128, 256>>>(hb);

    // 2) input projections (both directions), bias folded
    sgemm_xm_kernel<<<dim3(12, 256, 2), 256>>>(x, Wxf, Wxb, bf, bb, xm);

    // 3) 512 recurrence steps (fwd+bwd concurrently inside each step)
    for (int s = 0; s < TT; s++) {
        gru_step_kernel<<<dim3(64, 2), 256, STEP_SMEM_BYTES>>>(
            Whf, Whb, xm, hb, out, s);
    }
}

// round 2
// speedup vs baseline: 1.4354x; 1.4354x over previous
#include <cuda_runtime.h>
#include <cuda_bf16.h>
#include <cstdint>

// Problem constants
#define NB   64      // batch
#define TT   512     // time steps
#define DD   512     // input dim
#define HH   512     // hidden dim
#define G3   1536    // 3*H

// Scratch (device globals: allocation-free)
__device__ float g_xm[(size_t)2 * NB * TT * G3];   // [dir][n][t][3H], bias folded in
__device__ float g_h[2 * 2 * NB * HH];             // [dir][parity][n][h] ping-pong
__device__ unsigned g_arrive[2];
__device__ unsigned g_release[2];

// packed fp32x2 FMA (ptxas never auto-fuses this; PTX-only)
#define FMA2(d, a, b) asm("fma.rn.f32x2 %0, %1, %2, %0;" : "+l"(d) : "l"(a), "l"(b))

__device__ __forceinline__ float lo32(unsigned long long v) {
    return __uint_as_float((unsigned)(v & 0xffffffffull));
}
__device__ __forceinline__ float hi32(unsigned long long v) {
    return __uint_as_float((unsigned)(v >> 32));
}

// -----------------------------------------------------------------------------
// Init: zero h ping-pong buffers + barrier state
// -----------------------------------------------------------------------------
__global__ void init_kernel(float* h) {
    int i = blockIdx.x * blockDim.x + threadIdx.x;   // 128*256 = 32768 float4s
    reinterpret_cast<float4*>(h)[i] = make_float4(0.f, 0.f, 0.f, 0.f);
    if (i == 0) {
        g_arrive[0] = 0; g_arrive[1] = 0;
        g_release[0] = 0; g_release[1] = 0;
    }
}

// -----------------------------------------------------------------------------
// Input projection GEMM (unchanged from R1): xm = x @ Wx + b, both dirs.
// -----------------------------------------------------------------------------
#define BM 128
#define BN 128
#define BK 16

__global__ __launch_bounds__(256) void sgemm_xm_kernel(
    const float* __restrict__ x,
    const float* __restrict__ Wx_f, const float* __restrict__ Wx_b,
    const float* __restrict__ b_f,  const float* __restrict__ b_b,
    float* __restrict__ xm)
{
    const int dir = blockIdx.z;
    const float* __restrict__ Wx   = dir ? Wx_b : Wx_f;
    const float* __restrict__ bias = dir ? b_b  : b_f;
    float* __restrict__ C = xm + (size_t)dir * (NB * TT) * G3;

    __shared__ float As[BK][BM + 4];
    __shared__ float Bs[BK][BN];

    const int t  = threadIdx.x;
    const int tx = t & 15;
    const int ty = t >> 4;

    const int mBase = blockIdx.y * BM;
    const int nBase = blockIdx.x * BN;

    const int aRow = t >> 2;
    const int aK   = (t & 3) << 2;
    const int bRow = t >> 5;
    const int bCol = (t & 31) << 2;

    float acc[8][8];
#pragma unroll
    for (int i = 0; i < 8; i++)
#pragma unroll
        for (int j = 0; j < 8; j++) acc[i][j] = 0.f;

    for (int k0 = 0; k0 < DD; k0 += BK) {
#pragma unroll
        for (int h = 0; h < 2; h++) {
            const int m   = mBase + aRow + h * 64;
            const int n   = m >> 9;
            const int tt0 = m & 511;
            const int ts  = dir ? (TT - 1 - tt0) : tt0;
            const float4 v = *reinterpret_cast<const float4*>(
                &x[((size_t)n * TT + ts) * DD + k0 + aK]);
            As[aK + 0][aRow + h * 64] = v.x;
            As[aK + 1][aRow + h * 64] = v.y;
            As[aK + 2][aRow + h * 64] = v.z;
            As[aK + 3][aRow + h * 64] = v.w;
        }
#pragma unroll
        for (int h = 0; h < 2; h++) {
            const int kk = bRow + h * 8;
            *reinterpret_cast<float4*>(&Bs[kk][bCol]) =
                *reinterpret_cast<const float4*>(
                    &Wx[(size_t)(k0 + kk) * G3 + nBase + bCol]);
        }
        __syncthreads();

#pragma unroll
        for (int kk = 0; kk < BK; kk++) {
            float ra[8], rb[8];
#pragma unroll
            for (int i = 0; i < 8; i += 4) {
                float4 v = *reinterpret_cast<const float4*>(&As[kk][ty * 8 + i]);
                ra[i] = v.x; ra[i + 1] = v.y; ra[i + 2] = v.z; ra[i + 3] = v.w;
            }
#pragma unroll
            for (int j = 0; j < 8; j += 4) {
                float4 v = *reinterpret_cast<const float4*>(&Bs[kk][tx * 8 + j]);
                rb[j] = v.x; rb[j + 1] = v.y; rb[j + 2] = v.z; rb[j + 3] = v.w;
            }
#pragma unroll
            for (int i = 0; i < 8; i++)
#pragma unroll
                for (int j = 0; j < 8; j++)
                    acc[i][j] += ra[i] * rb[j];
        }
        __syncthreads();
    }

#pragma unroll
    for (int i = 0; i < 8; i++) {
        const int m = mBase + ty * 8 + i;
#pragma unroll
        for (int j = 0; j < 8; j += 4) {
            const int c = nBase + tx * 8 + j;
            float4 v;
            v.x = acc[i][j + 0] + bias[c + 0];
            v.y = acc[i][j + 1] + bias[c + 1];
            v.z = acc[i][j + 2] + bias[c + 2];
            v.w = acc[i][j + 3] + bias[c + 3];
            *reinterpret_cast<float4*>(&C[(size_t)m * G3 + c]) = v;
        }
    }
}

// -----------------------------------------------------------------------------
// Persistent recurrence kernel.
// Grid: dim3(64, 2) = 128 blocks, 256 threads. Block = (dir, 8 hidden units).
// SMEM:
//   w2t : 24 cols x 512 k floats (f32x2-pair layout along k)   = 48 KB (persistent)
//   h2  : 256 kp x 132 floats (64 n as f32x2 pairs, +4 pad)    = 135168 B (per step)
//   red : 24 x 64 floats split-K / gate staging                = 6 KB
// Per step: stage h (L2 broadcast), f32x2 GEMM (split-K=2 over warps),
// reduce, gates, per-direction global barrier.
// -----------------------------------------------------------------------------
#define W2T_FLOATS   (24 * 512)          // 12288
#define H2_ROW       132                 // 64*2 + 4 pad floats
#define H2_FLOATS    (256 * H2_ROW)      // 33792
#define RED_FLOATS   (24 * 64)           // 1536
#define PERSIST_SMEM ((W2T_FLOATS + H2_FLOATS + RED_FLOATS) * 4)

__global__ __launch_bounds__(256, 1) void gru_persist_kernel(
    const float* __restrict__ Wh_f, const float* __restrict__ Wh_b,
    const float* __restrict__ xm,   float* __restrict__ h_buf,
    float* __restrict__ out)
{
    extern __shared__ float sm[];
    float* w2t = sm;                          // [24][512]
    float* h2f = sm + W2T_FLOATS;             // [256][132]
    float* red = sm + W2T_FLOATS + H2_FLOATS; // [24][64]

    const int dir = blockIdx.y;
    const int j0  = blockIdx.x * 8;
    const float* __restrict__ Wh = dir ? Wh_b : Wh_f;
    const int t = threadIdx.x;

    // ---- load W slice once: w2t[c][k] = Wh[k][(c>>3)*512 + j0 + (c&7)] ----
    for (int idx = t; idx < 24 * 512; idx += 256) {
        const int c = idx >> 9;
        const int k = idx & 511;
        w2t[c * 512 + k] = Wh[(size_t)k * G3 + (c >> 3) * HH + j0 + (c & 7)];
    }
    __syncthreads();

    // fixed per-thread roles
    const int w    = t >> 5;        // warp
    const int l    = t & 31;        // lane
    const int half = w >> 2;        // split-K half
    const int cb   = (w & 3) * 6;   // column base (6 cols)

    // staging role: n_st = t>>2, 4 k-quads
    const int n_st = t >> 2;
    const int kq   = (t & 3) * 4;

    // gate role: pairs t and t+256 -> (n_g, jj) and (n_g+32, jj)
    const int n_g = t >> 3;
    const int jj  = t & 7;
    const int jgl = j0 + jj;

    const float* xmd = xm + (size_t)dir * (NB * TT) * G3;

    for (int s = 0; s < TT; s++) {
        const int p = s & 1;
        const float* __restrict__ hprev = h_buf + ((size_t)dir * 2 + p)       * (NB * HH);
        float*       __restrict__ hnext = h_buf + ((size_t)dir * 2 + (p ^ 1)) * (NB * HH);

        // ---- prefetch xm gate inputs for this step (consumed after GEMM) ----
        const float* xr0 = &xmd[(((size_t)n_g)        * TT + s) * G3 + jgl];
        const float* xr1 = &xmd[(((size_t)n_g + 32)   * TT + s) * G3 + jgl];
        const float pxz0 = __ldg(xr0);
        const float pxr0 = __ldg(xr0 + HH);
        const float pxg0 = __ldg(xr0 + 2 * HH);
        const float pxz1 = __ldg(xr1);
        const float pxr1 = __ldg(xr1 + HH);
        const float pxg1 = __ldg(xr1 + 2 * HH);

        // ---- stage h_prev into h2 (pair layout): h2[k>>1][2n + (k&1)] ----
#pragma unroll
        for (int k = kq; k < HH; k += 16) {
            const float4 v = *reinterpret_cast<const float4*>(&hprev[n_st * HH + k]);
            const int kp = k >> 1;
            *reinterpret_cast<float2*>(&h2f[kp * H2_ROW + 2 * n_st])       = make_float2(v.x, v.y);
            *reinterpret_cast<float2*>(&h2f[(kp + 1) * H2_ROW + 2 * n_st]) = make_float2(v.z, v.w);
        }
        __syncthreads();

        // ---- f32x2 GEMM: 6 cols x 2 n per thread, split-K over halves ----
        unsigned long long acc[12];
#pragma unroll
        for (int i = 0; i < 12; i++) acc[i] = 0ull;

        const int kpBeg = half * 128;
        for (int kp0 = kpBeg; kp0 < kpBeg + 128; kp0 += 4) {
            unsigned long long wv[6][4];
#pragma unroll
            for (int cc = 0; cc < 6; cc++) {
                const ulonglong2 wa = *reinterpret_cast<const ulonglong2*>(
                    &w2t[(cb + cc) * 512 + kp0 * 2]);
                const ulonglong2 wb = *reinterpret_cast<const ulonglong2*>(
                    &w2t[(cb + cc) * 512 + kp0 * 2 + 4]);
                wv[cc][0] = wa.x; wv[cc][1] = wa.y;
                wv[cc][2] = wb.x; wv[cc][3] = wb.y;
            }
#pragma unroll
            for (int q = 0; q < 4; q++) {
                const int kp = kp0 + q;
                const unsigned long long h0 =
                    *reinterpret_cast<const unsigned long long*>(&h2f[kp * H2_ROW + 2 * l]);
                const unsigned long long h1 =
                    *reinterpret_cast<const unsigned long long*>(&h2f[kp * H2_ROW + 2 * l + 64]);
#pragma unroll
                for (int cc = 0; cc < 6; cc++) {
                    FMA2(acc[cc * 2 + 0], wv[cc][q], h0);
                    FMA2(acc[cc * 2 + 1], wv[cc][q], h1);
                }
            }
        }

        // ---- split-K reduction into red[c][n] ----
        if (half == 1) {
#pragma unroll
            for (int cc = 0; cc < 6; cc++) {
                red[(cb + cc) * 64 + l]      = lo32(acc[cc * 2 + 0]) + hi32(acc[cc * 2 + 0]);
                red[(cb + cc) * 64 + l + 32] = lo32(acc[cc * 2 + 1]) + hi32(acc[cc * 2 + 1]);
            }
        }
        __syncthreads();
        if (half == 0) {
#pragma unroll
            for (int cc = 0; cc < 6; cc++) {
                const int i0 = (cb + cc) * 64 + l;
                const int i1 = i0 + 32;
                red[i0] = red[i0] + lo32(acc[cc * 2 + 0]) + hi32(acc[cc * 2 + 0]);
                red[i1] = red[i1] + lo32(acc[cc * 2 + 1]) + hi32(acc[cc * 2 + 1]);
            }
        }
        __syncthreads();

        // ---- gates: 2 (n, jj) pairs per thread ----
        const int t_out = dir ? (TT - 1 - s) : s;
        {
            const float hz0 = red[jj * 64 + n_g];
            const float hr0 = red[(8 + jj) * 64 + n_g];
            const float hg0 = red[(16 + jj) * 64 + n_g];
            const float hp0 = h2f[(jgl >> 1) * H2_ROW + 2 * n_g + (jgl & 1)];
            const float z0 = 1.f / (1.f + __expf(-(pxz0 + hz0)));
            const float r0 = 1.f / (1.f + __expf(-(pxr0 + hr0)));
            const float gg0 = tanhf(pxg0 + r0 * hg0);
            const float ht0 = (1.f - z0) * gg0 + z0 * hp0;
            hnext[n_g * HH + jgl] = ht0;
            out[((size_t)n_g * TT + t_out) * (2 * HH) + dir * HH + jgl] = ht0;

            const int n1 = n_g + 32;
            const float hz1 = red[jj * 64 + n1];
            const float hr1 = red[(8 + jj) * 64 + n1];
            const float hg1 = red[(16 + jj) * 64 + n1];
            const float hp1 = h2f[(jgl >> 1) * H2_ROW + 2 * n1 + (jgl & 1)];
            const float z1 = 1.f / (1.f + __expf(-(pxz1 + hz1)));
            const float r1 = 1.f / (1.f + __expf(-(pxr1 + hr1)));
            const float gg1 = tanhf(pxg1 + r1 * hg1);
            const float ht1 = (1.f - z1) * gg1 + z1 * hp1;
            hnext[n1 * HH + jgl] = ht1;
            out[((size_t)n1 * TT + t_out) * (2 * HH) + dir * HH + jgl] = ht1;
        }

        // ---- per-direction grid barrier (64 blocks) ----
        __syncthreads();              // all gate writes issued, h2 reads done
        __threadfence();              // publish hnext
        if (t == 0) {
            const unsigned old = atomicAdd(&g_arrive[dir], 1);
            if (old == 63) {
                g_arrive[dir] = 0;
                __threadfence();
                atomicExch(&g_release[dir], (unsigned)(s + 1));
            } else {
                while (*((volatile unsigned*)&g_release[dir]) < (unsigned)(s + 1)) { }
            }
        }
        __syncthreads();
        __threadfence();              // acquire: see peers' hnext
    }
}

// -----------------------------------------------------------------------------
// Launch
// -----------------------------------------------------------------------------
extern "C" void kernel_launch(void* const* d_in, const int* in_sizes, int n_in,
                              void* d_out, int out_size)
{
    (void)in_sizes; (void)n_in; (void)out_size;
    const float* x   = (const float*)d_in[0];
    const float* Wxf = (const float*)d_in[1];
    const float* Whf = (const float*)d_in[2];
    const float* bf  = (const float*)d_in[3];
    const float* Wxb = (const float*)d_in[4];
    const float* Whb = (const float*)d_in[5];
    const float* bb  = (const float*)d_in[6];
    float* out = (float*)d_out;

    float *xm, *hb;
    cudaGetSymbolAddress((void**)&xm, g_xm);
    cudaGetSymbolAddress((void**)&hb, g_h);

    cudaFuncSetAttribute(gru_persist_kernel,
                         cudaFuncAttributeMaxDynamicSharedMemorySize,
                         PERSIST_SMEM);

    // 1) h0 = 0, barrier state = 0
    init_kernel<<<128, 256>>>(hb);

    // 2) input projections (both directions), bias folded
    sgemm_xm_kernel<<<dim3(12, 256, 2), 256>>>(x, Wxf, Wxb, bf, bb, xm);

    // 3) persistent recurrence (all 512 steps, both dirs)
    gru_persist_kernel<<<dim3(64, 2), 256, PERSIST_SMEM>>>(
        Whf, Whb, xm, hb, out);
}